// round 17
// baseline (speedup 1.0000x reference)
#include <cuda_runtime.h>
#include <cuda_fp16.h>
#include <cstdint>
#include <math.h>

constexpr int NN   = 8192;
constexpr int IND  = 512;
constexpr int HIDD = 256;
constexpr int OUTD = 128;

// Tile geometry: 128 rows x 32 k-elems.
// Global frag tiles: PACKED, 16 words/row (2048 words = 8KB per tile).
// Smem tiles: padded to 20 words/row (2560 words) for conflict-free LDS.
constexpr int TGW     = 16;                 // global words per row (packed)
constexpr int TILE_GW = 128 * TGW;          // 2048 words per global tile
constexpr int TKW     = 20;                 // smem words per row (padded)
constexpr int TILE_W  = 128 * TKW;          // 2560 words per smem tile
constexpr int STAGE_B = 2 * TILE_W * 4;     // A + B smem stage = 20480 B
constexpr int NSTAGE  = 3;
constexpr int SMEM_DYN = NSTAGE * STAGE_B;  // 61440 B

// Scratch (__device__ globals: allocation-free rule)
__device__ __align__(128) float    g_h1 [NN * HIDD];
__device__ __align__(128) float    g_part[4 * NN * OUTD];
// Packed fp16 frag arrays (smem-image tiles, 16 words/row)
__device__ __align__(128) uint32_t g_Ah[(size_t)64 * 256 * TILE_GW];  // adj (134MB)
__device__ __align__(128) uint32_t g_B1[(size_t)2 * 256 * TILE_GW];   // t1
__device__ __align__(128) uint32_t g_B2[(size_t)1 * 256 * TILE_GW];   // t2
__device__ __align__(128) uint32_t g_Bh[(size_t)64 * 4 * TILE_GW];    // h

enum { EPI_NONE = 0, EPI_SIGMOID = 1 };

// ===========================================================================
// Helpers (baseline sm_80+ PTX — compiles under compute_103)
// ===========================================================================
__device__ __forceinline__ uint32_t smem_u32(const void* p) {
    uint32_t a;
    asm("{ .reg .u64 t; cvta.to.shared.u64 t, %1; cvt.u32.u64 %0, t; }" : "=r"(a) : "l"(p));
    return a;
}
__device__ __forceinline__ uint32_t pack_h2(float lo_elem, float hi_elem) {
    uint32_t r;
    asm("cvt.rn.f16x2.f32 %0, %1, %2;" : "=r"(r) : "f"(hi_elem), "f"(lo_elem));
    return r;
}
__device__ __forceinline__ uint2 pack4h(float4 v) {
    uint2 h;
    h.x = pack_h2(v.x, v.y);
    h.y = pack_h2(v.z, v.w);
    return h;
}
__device__ __forceinline__ void mma_f16(float* c, const uint32_t* a, const uint32_t* b) {
    asm volatile(
        "mma.sync.aligned.m16n8k16.row.col.f32.f16.f16.f32 "
        "{%0,%1,%2,%3}, {%4,%5,%6,%7}, {%8,%9}, {%0,%1,%2,%3};"
        : "+f"(c[0]), "+f"(c[1]), "+f"(c[2]), "+f"(c[3])
        : "r"(a[0]), "r"(a[1]), "r"(a[2]), "r"(a[3]), "r"(b[0]), "r"(b[1]));
}
__device__ __forceinline__ void cpasync16(uint32_t dst, const void* src) {
    asm volatile("cp.async.ca.shared.global [%0], [%1], 16;" :: "r"(dst), "l"(src) : "memory");
}
__device__ __forceinline__ void cp_commit() {
    asm volatile("cp.async.commit_group;" ::: "memory");
}
__device__ __forceinline__ void cp_wait1() {
    asm volatile("cp.async.wait_group 1;" ::: "memory");
}
__device__ __forceinline__ void cp_wait0() {
    asm volatile("cp.async.wait_group 0;" ::: "memory");
}
__device__ __forceinline__ void st_cs_f2(float* p, float2 v) {
    asm volatile("st.global.cs.v2.f32 [%0], {%1, %2};" :: "l"(p), "f"(v.x), "f"(v.y) : "memory");
}

// Packed global frag word offset for element (n, k); KTt = K/32
__device__ __forceinline__ size_t bfrag_off(int n, int k0, int KTt) {
    return ((size_t)(n >> 7) * KTt + (k0 >> 5)) * TILE_GW
         + (size_t)(n & 127) * TGW + ((k0 & 31) >> 1);
}

// MUFU-free sigmoid (full path; only for |x| < 17)
__device__ __forceinline__ float fast_sigmoid(float x) {
    const float L2E = 1.4426950408889634f;
    float ax = fabsf(x);
    float t  = fminf(ax * L2E, 126.0f);
    float u  = -t;
    float fi = floorf(u);
    float f  = u - fi;
    float p = 1.5252733804059838e-5f;
    p = fmaf(p, f, 1.5403530393381608e-4f);
    p = fmaf(p, f, 1.3333558146428443e-3f);
    p = fmaf(p, f, 9.6181291076284770e-3f);
    p = fmaf(p, f, 5.5504108664821580e-2f);
    p = fmaf(p, f, 2.4022650695910071e-1f);
    p = fmaf(p, f, 6.9314718055994531e-1f);
    p = fmaf(p, f, 1.0f);
    float scale = __int_as_float(((int)fi + 127) << 23);
    float e = p * scale;
    float d = 1.0f + e;
    float r = fmaf(e, fmaf(e, 0.3241f, -0.8104f), 0.9909f);
    r = r * fmaf(-d, r, 2.0f);
    r = r * fmaf(-d, r, 2.0f);
    return (x >= 0.0f) ? r : e * r;
}
__device__ __forceinline__ void sigmoid4_sat(float& a, float& b, float& c, float& d) {
    float mn = fminf(fminf(fabsf(a), fabsf(b)), fminf(fabsf(c), fabsf(d)));
    if (mn >= 17.0f) {
        a = a > 0.0f ? 1.0f : 0.0f;
        b = b > 0.0f ? 1.0f : 0.0f;
        c = c > 0.0f ? 1.0f : 0.0f;
        d = d > 0.0f ? 1.0f : 0.0f;
    } else {
        a = fast_sigmoid(a);
        b = fast_sigmoid(b);
        c = fast_sigmoid(c);
        d = fast_sigmoid(d);
    }
}

// ===========================================================================
// Prep: adj fp32 [8192,8192] -> packed fp16 frag tiles (one-time conversion).
// CTA = one 128x32 tile. Reads coalesced float4, writes 64B row-runs.
// ===========================================================================
__global__ __launch_bounds__(256)
void adj2h_k(const float* __restrict__ adj, uint32_t* __restrict__ fr)
{
    const int kt = blockIdx.x;          // 0..255
    const int rb = blockIdx.y;          // 0..63
    const int tid = threadIdx.x;
    uint32_t* dst = fr + ((size_t)rb * 256 + kt) * TILE_GW;
#pragma unroll
    for (int i = 0; i < 4; i++) {
        int l = tid + i * 256;          // 1024 float4 slots
        int r = l >> 3, c4 = l & 7;
        float4 v = *reinterpret_cast<const float4*>(
            &adj[(size_t)(rb * 128 + r) * NN + kt * 32 + c4 * 4]);
        *reinterpret_cast<uint2*>(&dst[r * TGW + c4 * 2]) = pack4h(v);
    }
}

// ===========================================================================
// fp16 tensor GEMM: C[128y,128x] = epi( A[M,K] @ B[N,K]^T )
// BOTH operands are packed fp16 frag arrays, filled via a 3-stage
// cp.async pipeline (fills issued 2 iterations ahead -> latency budget
// ~2 mma blocks >= DRAM latency; this was the R14/R15 stall).
// ===========================================================================
template <int EPI>
__global__ __launch_bounds__(256, 2)
void tgemm(const uint32_t* __restrict__ Afr, const uint32_t* __restrict__ Bfr,
           float* __restrict__ C, int ldc, size_t partStride, int K, int kSplit)
{
    extern __shared__ __align__(16) uint32_t sm[];
    const int tid  = threadIdx.x;
    const int lane = tid & 31;
    const int wid  = tid >> 5;
    const int warpM = wid & 1;          // 2 warp-rows of 64
    const int warpN = wid >> 1;         // 4 warp-cols of 32
    const int g = lane >> 2;
    const int t = lane & 3;

    const int rowBase = blockIdx.y * 128;
    const int colBase = blockIdx.x * 128;
    const int KTtot   = K >> 5;
    const int KT      = kSplit >> 5;
    const int kt0     = blockIdx.z * KT;
    float* Cz = C + (size_t)blockIdx.z * partStride;
    const uint32_t sbase = smem_u32(sm);

    float acc[4][4][4];
#pragma unroll
    for (int i = 0; i < 4; i++)
#pragma unroll
        for (int j = 0; j < 4; j++)
#pragma unroll
            for (int q = 0; q < 4; q++) acc[i][j][q] = 0.0f;

    // Fill stage s with k-tile kt: 1024 16B chunks (512 A + 512 B).
    // src packed (16B-contiguous per row), dst padded smem rows.
    auto fill = [&](int kt, int s) {
        const char* sa = (const char*)(Afr +
            ((size_t)(rowBase >> 7) * KTtot + (kt0 + kt)) * TILE_GW);
        const char* sb = (const char*)(Bfr +
            ((size_t)blockIdx.x * KTtot + (kt0 + kt)) * TILE_GW);
        uint32_t dA = sbase + (uint32_t)s * STAGE_B;
        uint32_t dB = dA + TILE_W * 4;
#pragma unroll
        for (int i = 0; i < 4; i++) {
            int c = tid + i * 256;              // 0..1023
            bool isA = (c < 512);
            int cc = isA ? c : (c - 512);
            int r = cc >> 2, c16 = cc & 3;
            uint32_t dst = (isA ? dA : dB) + (uint32_t)(r * TKW * 4 + c16 * 16);
            const char* src = (isA ? sa : sb) + (size_t)cc * 16;
            cpasync16(dst, src);
        }
        cp_commit();
    };

    // Prologue: stages 0,1
    fill(0, 0);
    if (KT > 1) fill(1, 1);
    else cp_commit();                    // keep group count uniform

    for (int kt = 0; kt < KT; ++kt) {
        if (kt + 1 < KT) cp_wait1(); else cp_wait0();
        __syncthreads();                 // all warps done mma(kt-1); stage kt visible
        if (kt + 2 < KT) fill(kt + 2, (kt + 2) % NSTAGE);

        const uint32_t* Ah = sm + (kt % NSTAGE) * (STAGE_B / 4);
        const uint32_t* Bh = Ah + TILE_W;

#pragma unroll
        for (int s8 = 0; s8 < 2; s8++) {  // two k16 steps per 32-k tile
            uint32_t bh[4][2];
#pragma unroll
            for (int nt = 0; nt < 4; nt++) {
                int o = (warpN * 32 + nt * 8 + g) * TKW + s8 * 8 + t;
                bh[nt][0] = Bh[o]; bh[nt][1] = Bh[o + 4];
            }
#pragma unroll
            for (int mt = 0; mt < 4; mt++) {
                int o = (warpM * 64 + mt * 16 + g) * TKW + s8 * 8 + t;
                uint32_t ah[4] = {Ah[o], Ah[o + 8 * TKW], Ah[o + 4], Ah[o + 8 * TKW + 4]};
#pragma unroll
                for (int nt = 0; nt < 4; nt++)
                    mma_f16(acc[mt][nt], ah, bh[nt]);
            }
        }
    }

    // Epilogue: direct fragment stores (float2; .cs streaming for sigmoid out)
#pragma unroll
    for (int mt = 0; mt < 4; mt++) {
        const int row = rowBase + warpM * 64 + mt * 16 + g;
#pragma unroll
        for (int nt = 0; nt < 4; nt++) {
            const int col = colBase + warpN * 32 + nt * 8 + t * 2;
            float2 v0, v1;
            v0.x = acc[mt][nt][0]; v0.y = acc[mt][nt][1];
            v1.x = acc[mt][nt][2]; v1.y = acc[mt][nt][3];
            if (EPI == EPI_SIGMOID) {
                sigmoid4_sat(v0.x, v0.y, v1.x, v1.y);
                st_cs_f2(&Cz[(size_t)row * ldc + col], v0);
                st_cs_f2(&Cz[(size_t)(row + 8) * ldc + col], v1);
            } else {
                *reinterpret_cast<float2*>(&Cz[(size_t)row * ldc + col])       = v0;
                *reinterpret_cast<float2*>(&Cz[(size_t)(row + 8) * ldc + col]) = v1;
            }
        }
    }
}

// ===========================================================================
// Split-K combine: out = sum_s p[s] + bias (+relu); FRAG also emits the fp16
// packed frag tile of the result (h -> G5 operands).
// ===========================================================================
template <int S, bool RELU, bool FRAG>
__global__ void combine_k(const float* __restrict__ p, size_t stride,
                          const float* __restrict__ bias, float* __restrict__ o,
                          int ncols4, uint32_t* __restrict__ fr)
{
    int i = blockIdx.x * blockDim.x + threadIdx.x;
    float4 a = reinterpret_cast<const float4*>(p)[i];
#pragma unroll
    for (int s = 1; s < S; s++) {
        float4 b = reinterpret_cast<const float4*>(p + (size_t)s * stride)[i];
        a.x += b.x; a.y += b.y; a.z += b.z; a.w += b.w;
    }
    float4 bb = reinterpret_cast<const float4*>(bias)[i % ncols4];
    a.x += bb.x; a.y += bb.y; a.z += bb.z; a.w += bb.w;
    if (RELU) {
        a.x = fmaxf(a.x, 0.0f); a.y = fmaxf(a.y, 0.0f);
        a.z = fmaxf(a.z, 0.0f); a.w = fmaxf(a.w, 0.0f);
    }
    reinterpret_cast<float4*>(o)[i] = a;
    if (FRAG) {
        int j  = i >> 5;              // node row (OUTD=128 -> 32 float4/row)
        int k0 = (i & 31) * 4;
        size_t w = bfrag_off(j, k0, OUTD / 32);
        *reinterpret_cast<uint2*>(&fr[w]) = pack4h(a);
    }
}

// ===========================================================================
// SIMT fp32 GEMM (G1, G3): A@B then emit packed fp16 frag layout
// (n = output col, k = output row) via smem-staged transpose.
// ===========================================================================
template <int BM, int BN, int BK, int TM, int TN>
__global__ __launch_bounds__((BM / TM) * (BN / TN))
void gemm_frag_k(const float* __restrict__ A, const float* __restrict__ B,
                 uint32_t* __restrict__ fr, int M, int Ncols, int K)
{
    constexpr int THREADS = (BM / TM) * (BN / TN);
    __shared__ float As[BK][BM + 4];
    __shared__ float Bs[BK][BN];
    __shared__ float Tr[BN][BM + 4];

    const int tid = threadIdx.x;
    const int tx  = tid % (BN / TN);
    const int ty  = tid / (BN / TN);
    const int rowBase = blockIdx.y * BM;
    const int colBase = blockIdx.x * BN;

    float acc[TM][TN];
#pragma unroll
    for (int i = 0; i < TM; i++)
#pragma unroll
        for (int j = 0; j < TN; j++) acc[i][j] = 0.0f;

    constexpr int A_IT = BM * BK / 4 / THREADS;
    constexpr int B_IT = BK * BN / 4 / THREADS;

    for (int k0 = 0; k0 < K; k0 += BK) {
#pragma unroll
        for (int i = 0; i < A_IT; i++) {
            int linear = tid + i * THREADS;
            int r = linear / (BK / 4), c4 = linear % (BK / 4);
            float4 v = *reinterpret_cast<const float4*>(&A[(size_t)(rowBase + r) * K + k0 + c4 * 4]);
            As[c4 * 4 + 0][r] = v.x; As[c4 * 4 + 1][r] = v.y;
            As[c4 * 4 + 2][r] = v.z; As[c4 * 4 + 3][r] = v.w;
        }
#pragma unroll
        for (int i = 0; i < B_IT; i++) {
            int linear = tid + i * THREADS;
            int r = linear / (BN / 4), c4 = linear % (BN / 4);
            *reinterpret_cast<float4*>(&Bs[r][c4 * 4]) =
                *reinterpret_cast<const float4*>(&B[(size_t)(k0 + r) * Ncols + colBase + c4 * 4]);
        }
        __syncthreads();
#pragma unroll
        for (int k = 0; k < BK; k++) {
            float ra[TM], rb[TN];
#pragma unroll
            for (int i = 0; i < TM; i += 4) {
                float4 v = *reinterpret_cast<const float4*>(&As[k][ty * TM + i]);
                ra[i] = v.x; ra[i + 1] = v.y; ra[i + 2] = v.z; ra[i + 3] = v.w;
            }
#pragma unroll
            for (int j = 0; j < TN; j += 4) {
                float4 v = *reinterpret_cast<const float4*>(&Bs[k][tx * TN + j]);
                rb[j] = v.x; rb[j + 1] = v.y; rb[j + 2] = v.z; rb[j + 3] = v.w;
            }
#pragma unroll
            for (int i = 0; i < TM; i++)
#pragma unroll
                for (int j = 0; j < TN; j++)
                    acc[i][j] = fmaf(ra[i], rb[j], acc[i][j]);
        }
        __syncthreads();
    }

#pragma unroll
    for (int i = 0; i < TM; i++)
#pragma unroll
        for (int j = 0; j < TN; j++)
            Tr[tx * TN + j][ty * TM + i] = acc[i][j];
    __syncthreads();

    const int KTt = M / 32;
    constexpr int ST_IT = BM * BN / 4 / THREADS;
#pragma unroll
    for (int it = 0; it < ST_IT; it++) {
        int linear = tid + it * THREADS;
        int c  = linear / (BM / 4);
        int r4 = linear % (BM / 4);
        float4 v = *reinterpret_cast<const float4*>(&Tr[c][r4 * 4]);
        size_t w = bfrag_off(colBase + c, rowBase + r4 * 4, KTt);
        *reinterpret_cast<uint2*>(&fr[w]) = pack4h(v);
    }
}

// ===========================================================================
// Launch
// ===========================================================================
extern "C" void kernel_launch(void* const* d_in, const int* in_sizes, int n_in,
                              void* d_out, int out_size)
{
    const float* adj     = (const float*)d_in[0];
    const float* feature = (const float*)d_in[1];
    const float* W1      = (const float*)d_in[2];
    const float* b1      = (const float*)d_in[3];
    const float* W2      = (const float*)d_in[4];
    const float* b2      = (const float*)d_in[5];

    float* out   = (float*)d_out;                    // sigmoid(h@h^T): NN*NN
    float* h_out = (float*)d_out + (size_t)NN * NN;  // h: NN*OUTD

    float *h1, *part;
    uint32_t *Ah, *B1, *B2, *Bh;
    cudaGetSymbolAddress((void**)&h1,   g_h1);
    cudaGetSymbolAddress((void**)&part, g_part);
    cudaGetSymbolAddress((void**)&Ah,   g_Ah);
    cudaGetSymbolAddress((void**)&B1,   g_B1);
    cudaGetSymbolAddress((void**)&B2,   g_B2);
    cudaGetSymbolAddress((void**)&Bh,   g_Bh);

    cudaFuncSetAttribute((const void*)tgemm<EPI_NONE>,
                         cudaFuncAttributeMaxDynamicSharedMemorySize, SMEM_DYN);
    cudaFuncSetAttribute((const void*)tgemm<EPI_SIGMOID>,
                         cudaFuncAttributeMaxDynamicSharedMemorySize, SMEM_DYN);

    // Prep: adj -> packed fp16 frag tiles (one-time)
    adj2h_k<<<dim3(256, 64), 256>>>(adj, Ah);

    // G1: t1 = feature @ W1 -> packed fp16 frag
    gemm_frag_k<64, 64, 16, 4, 4>
        <<<dim3(HIDD / 64, NN / 64), 256>>>(feature, W1, B1, NN, HIDD, IND);

    // G2: partials of adj @ t1^T  (split-K=2, 3-stage cp.async pipeline)
    tgemm<EPI_NONE><<<dim3(HIDD / 128, NN / 128, 2), 256, SMEM_DYN>>>(
        Ah, B1, part, HIDD, (size_t)NN * HIDD, NN, NN / 2);

    // h1 = relu(p0 + p1 + b1)
    combine_k<2, true, false><<<(NN * HIDD / 4) / 256, 256>>>(
        part, (size_t)NN * HIDD, b1, h1, HIDD / 4, nullptr);

    // G3: t2 = h1 @ W2 -> packed fp16 frag
    gemm_frag_k<64, 64, 16, 4, 4>
        <<<dim3(OUTD / 64, NN / 64), 256>>>(h1, W2, B2, NN, OUTD, HIDD);

    // G4: partials of adj @ t2^T  (split-K=4)
    tgemm<EPI_NONE><<<dim3(OUTD / 128, NN / 128, 4), 256, SMEM_DYN>>>(
        Ah, B2, part, OUTD, (size_t)NN * OUTD, NN, NN / 4);

    // h = p0+p1+p2+p3 + b2  (also emits h packed frag for G5)
    combine_k<4, false, true><<<(NN * OUTD / 4) / 256, 256>>>(
        part, (size_t)NN * OUTD, b2, h_out, OUTD / 4, Bh);

    // G5: out = sigmoid(h @ h^T) — both operands from the h frag array
    tgemm<EPI_SIGMOID><<<dim3(NN / 128, NN / 128, 1), 256, SMEM_DYN>>>(
        Bh, Bh, out, NN, 0, OUTD, OUTD);
}